// round 2
// baseline (speedup 1.0000x reference)
#include <cuda_runtime.h>
#include <cstdint>

// ---------------- config ----------------
#define CTAS          1024
#define THREADS       256
#define ROWS_PER_CTA  1024          // 1024*1024 = 1,048,576 rows
#define CHUNK_ROWS    256
#define NCHUNKS       4             // ROWS_PER_CTA / CHUNK_ROWS
#define ROW_STRIDE_B  272           // 68 floats: pad for conflict-free LDS

// smem layout (bytes)
#define SMEM_W      0
#define W_BYTES     (64 * ROW_STRIDE_B)          // 17408
#define SMEM_X      W_BYTES
#define STAGE_BYTES (CHUNK_ROWS * ROW_STRIDE_B)  // 69632
#define SMEM_TOTAL  (SMEM_X + 2 * STAGE_BYTES)   // 156672

// ---------------- math constants ----------------
// v = clamp(3*z, -10, 10); exp(v) = exp2(clamp(z*3*log2e, +/-10*log2e))
#define C_SCALE_L2E  4.3280851227f   // 3 * log2(e)
#define C_CLAMP_L2E 14.4269504089f   // 10 * log2(e)
#define C_LN2        0.6931471806f

// ---------------- helpers ----------------
static __device__ __forceinline__ uint32_t smem_u32(const void* p) {
    uint32_t a;
    asm("{ .reg .u64 t; cvta.to.shared.u64 t, %1; cvt.u32.u64 %0, t; }"
        : "=r"(a) : "l"(p));
    return a;
}
static __device__ __forceinline__ void cp16(uint32_t s, const void* g) {
    asm volatile("cp.async.cg.shared.global [%0], [%1], 16;" :: "r"(s), "l"(g));
}
#define CP_COMMIT() asm volatile("cp.async.commit_group;" ::: "memory")
#define CP_WAIT1()  asm volatile("cp.async.wait_group 1;" ::: "memory")

static __device__ __forceinline__ float exp2_fast(float x) {
    float r; asm("ex2.approx.ftz.f32 %0, %1;" : "=f"(r) : "f"(x)); return r;
}
static __device__ __forceinline__ float lg2_fast(float x) {
    float r; asm("lg2.approx.f32 %0, %1;" : "=f"(r) : "f"(x)); return r;
}
static __device__ __forceinline__ float rcp_fast(float x) {
    float r; asm("rcp.approx.ftz.f32 %0, %1;" : "=f"(r) : "f"(x)); return r;
}
static __device__ __forceinline__ uint32_t f2tf32(float v) {
    uint32_t r; asm("cvt.rna.tf32.f32 %0, %1;" : "=r"(r) : "f"(v)); return r;
}
static __device__ __forceinline__ uint32_t lds32(const char* smem, uint32_t off) {
    return *reinterpret_cast<const uint32_t*>(smem + off);
}

// mma.sync m16n8k8 tf32: D = A(16x8 row) * B(8x8, B[k][n] with n-major regs) + D
static __device__ __forceinline__ void mma_tf32(
    float* d, const uint32_t* a, const uint32_t* b) {
    asm volatile(
        "mma.sync.aligned.m16n8k8.row.col.f32.tf32.tf32.f32 "
        "{%0,%1,%2,%3}, {%4,%5,%6,%7}, {%8,%9}, {%0,%1,%2,%3};"
        : "+f"(d[0]), "+f"(d[1]), "+f"(d[2]), "+f"(d[3])
        : "r"(a[0]), "r"(a[1]), "r"(a[2]), "r"(a[3]), "r"(b[0]), "r"(b[1]));
}

// exp(clamp(3*z)) via exp2
static __device__ __forceinline__ float expv(float z) {
    float w = fminf(fmaxf(z * C_SCALE_L2E, -C_CLAMP_L2E), C_CLAMP_L2E);
    return exp2_fast(w);
}
// mish(ln s) with e^(ln s) == s exactly:  lse * ((1+s)^2-1)/((1+s)^2+1)
static __device__ __forceinline__ float mish_of_ln(float s) {
    float lse = C_LN2 * lg2_fast(s);
    float up  = s + 1.0f;
    float q   = up * up;
    return lse * (q - 1.0f) * rcp_fast(q + 1.0f);
}

// ---------------- kernel ----------------
__global__ void __launch_bounds__(THREADS, 1) fused_lin_lse_mish(
    const float* __restrict__ x, const float* __restrict__ W,
    float* __restrict__ out) {
    extern __shared__ char smem[];
    const uint32_t sb  = smem_u32(smem);
    const int tid  = threadIdx.x;
    const int lane = tid & 31;
    const int w    = tid >> 5;          // warp 0..7
    const int g    = lane >> 2;         // group id (row within fragment)
    const int t    = lane & 3;          // thread-in-group (col within fragment)

    // ---- W -> smem (tf32, stride-68-float padded rows) ----
#pragma unroll
    for (int i = 0; i < 16; i++) {
        int idx = i * THREADS + tid;    // 4096 elems
        int r = idx >> 6, c = idx & 63;
        *reinterpret_cast<uint32_t*>(smem + SMEM_W + r * ROW_STRIDE_B + c * 4)
            = f2tf32(W[idx]);
    }

    const size_t row0 = (size_t)blockIdx.x * ROWS_PER_CTA;

    // ---- prologue: fill both stages ----
#pragma unroll
    for (int s = 0; s < 2; s++) {
        const float* src = x + (row0 + (size_t)s * CHUNK_ROWS) * 64;
        uint32_t sbase = sb + SMEM_X + (uint32_t)s * STAGE_BYTES;
#pragma unroll
        for (int i = 0; i < 16; i++) {
            int idx = i * THREADS + tid;       // 4096 16B-chunks per stage
            int r = idx >> 4, c = idx & 15;
            cp16(sbase + (uint32_t)(r * ROW_STRIDE_B + c * 16),
                 src + (size_t)r * 64 + c * 4);
        }
        CP_COMMIT();
    }

    // per-warp invariant bases
    const uint32_t b_base = (uint32_t)(SMEM_W + g * ROW_STRIDE_B + t * 4);

    for (int c = 0; c < NCHUNKS; c++) {
        CP_WAIT1();
        __syncthreads();                 // chunk c resident for all warps

        const uint32_t xs = (uint32_t)(SMEM_X + (c & 1) * STAGE_BYTES);
        const uint32_t a_base = xs + (uint32_t)((w * 32 + g) * ROW_STRIDE_B + t * 4);

        float acc[2][8][4];
#pragma unroll
        for (int mt = 0; mt < 2; mt++)
#pragma unroll
            for (int nb = 0; nb < 8; nb++)
#pragma unroll
                for (int j = 0; j < 4; j++) acc[mt][nb][j] = 0.0f;

#pragma unroll
        for (int kb = 0; kb < 8; kb++) {
            uint32_t a[2][4];
#pragma unroll
            for (int mt = 0; mt < 2; mt++) {
                uint32_t ab = a_base + (uint32_t)(mt * 16 * ROW_STRIDE_B + kb * 32);
                a[mt][0] = lds32(smem, ab);
                a[mt][1] = lds32(smem, ab + 8 * ROW_STRIDE_B);
                a[mt][2] = lds32(smem, ab + 16);
                a[mt][3] = lds32(smem, ab + 8 * ROW_STRIDE_B + 16);
            }
            uint32_t b[8][2];
            uint32_t bb = b_base + (uint32_t)(kb * 32);
#pragma unroll
            for (int nb = 0; nb < 8; nb++) {
                b[nb][0] = lds32(smem, bb + nb * 8 * ROW_STRIDE_B);
                b[nb][1] = lds32(smem, bb + nb * 8 * ROW_STRIDE_B + 16);
            }
#pragma unroll
            for (int mt = 0; mt < 2; mt++)
#pragma unroll
                for (int nb = 0; nb < 8; nb++)
                    mma_tf32(acc[mt][nb], a[mt], b[nb]);
        }

        // ---- epilogue: rows (w*32 + mt*16 + g) and (+8) ----
#pragma unroll
        for (int mt = 0; mt < 2; mt++) {
            float sl = 0.0f, sh = 0.0f;
#pragma unroll
            for (int nb = 0; nb < 8; nb++) {
                sl += expv(acc[mt][nb][0]) + expv(acc[mt][nb][1]);
                sh += expv(acc[mt][nb][2]) + expv(acc[mt][nb][3]);
            }
            // reduce across the 4 threads of the quad (lanes differ in t only)
            sl += __shfl_xor_sync(0xFFFFFFFF, sl, 1);
            sl += __shfl_xor_sync(0xFFFFFFFF, sl, 2);
            sh += __shfl_xor_sync(0xFFFFFFFF, sh, 1);
            sh += __shfl_xor_sync(0xFFFFFFFF, sh, 2);
            if (t == 0) {
                size_t row = row0 + (size_t)c * CHUNK_ROWS + w * 32 + mt * 16 + g;
                out[row]     = mish_of_ln(sl);
                out[row + 8] = mish_of_ln(sh);
            }
        }

        __syncthreads();                 // stage (c&1) fully consumed
        if (c + 2 < NCHUNKS) {
            const float* src = x + (row0 + (size_t)(c + 2) * CHUNK_ROWS) * 64;
            uint32_t sbase = sb + SMEM_X + (uint32_t)((c & 1)) * STAGE_BYTES;
#pragma unroll
            for (int i = 0; i < 16; i++) {
                int idx = i * THREADS + tid;
                int r = idx >> 4, cc = idx & 15;
                cp16(sbase + (uint32_t)(r * ROW_STRIDE_B + cc * 16),
                     src + (size_t)r * 64 + cc * 4);
            }
        }
        CP_COMMIT();                     // always commit (empty ok) for uniform counts
    }
}

// ---------------- launch ----------------
extern "C" void kernel_launch(void* const* d_in, const int* in_sizes, int n_in,
                              void* d_out, int out_size) {
    (void)in_sizes; (void)n_in; (void)out_size;
    const float* x = (const float*)d_in[0];
    const float* W = (const float*)d_in[1];
    float* out = (float*)d_out;

    cudaFuncSetAttribute(fused_lin_lse_mish,
                         cudaFuncAttributeMaxDynamicSharedMemorySize, SMEM_TOTAL);
    fused_lin_lse_mish<<<CTAS, THREADS, SMEM_TOTAL>>>(x, W, out);
}

// round 3
// speedup vs baseline: 1.2952x; 1.2952x over previous
#include <cuda_runtime.h>
#include <cstdint>

// ---------------- config ----------------
#define CTAS          2048
#define THREADS       256
#define WARPS         8
#define ROWS_PER_CTA  512            // 2048*512 = 1,048,576
#define CHUNK         16             // rows per warp-chunk
#define NCHUNK        4              // 4*16 = 64 rows per warp
#define STAGES        3

// smem layout (bytes): W (swizzled, 16 KB) then per-warp triple buffers
#define WBYTES      16384            // 64 rows x 256 B
#define TILE_BYTES  (CHUNK * 256)    // 4096
#define SMEM_X      WBYTES
#define SMEM_TOTAL  (WBYTES + WARPS * STAGES * TILE_BYTES)   // 114688

// ---------------- math constants ----------------
#define C_SCALE_L2E  4.3280851227f   // 3 * log2(e)
#define C_CLAMP_L2E 14.4269504089f   // 10 * log2(e)
#define C_LN2        0.6931471806f

// ---------------- helpers ----------------
static __device__ __forceinline__ uint32_t smem_u32(const void* p) {
    uint32_t a;
    asm("{ .reg .u64 t; cvta.to.shared.u64 t, %1; cvt.u32.u64 %0, t; }"
        : "=r"(a) : "l"(p));
    return a;
}
static __device__ __forceinline__ void cp16(uint32_t s, const void* g) {
    asm volatile("cp.async.cg.shared.global [%0], [%1], 16;" :: "r"(s), "l"(g));
}
#define CP_COMMIT() asm volatile("cp.async.commit_group;" ::: "memory")
#define CP_WAIT2()  asm volatile("cp.async.wait_group 2;" ::: "memory")

static __device__ __forceinline__ float exp2_fast(float x) {
    float r; asm("ex2.approx.ftz.f32 %0, %1;" : "=f"(r) : "f"(x)); return r;
}
static __device__ __forceinline__ float lg2_fast(float x) {
    float r; asm("lg2.approx.f32 %0, %1;" : "=f"(r) : "f"(x)); return r;
}
static __device__ __forceinline__ float rcp_fast(float x) {
    float r; asm("rcp.approx.ftz.f32 %0, %1;" : "=f"(r) : "f"(x)); return r;
}
static __device__ __forceinline__ uint32_t f2tf32(float v) {
    uint32_t r; asm("cvt.rna.tf32.f32 %0, %1;" : "=r"(r) : "f"(v)); return r;
}
static __device__ __forceinline__ uint32_t lds32(const char* smem, uint32_t off) {
    return *reinterpret_cast<const uint32_t*>(smem + off);
}

// mma.sync m16n8k8 tf32
static __device__ __forceinline__ void mma_tf32(
    float* d, const uint32_t* a, const uint32_t* b) {
    asm volatile(
        "mma.sync.aligned.m16n8k8.row.col.f32.tf32.tf32.f32 "
        "{%0,%1,%2,%3}, {%4,%5,%6,%7}, {%8,%9}, {%0,%1,%2,%3};"
        : "+f"(d[0]), "+f"(d[1]), "+f"(d[2]), "+f"(d[3])
        : "r"(a[0]), "r"(a[1]), "r"(a[2]), "r"(a[3]), "r"(b[0]), "r"(b[1]));
}

static __device__ __forceinline__ float expv(float z) {
    float w = fminf(fmaxf(z * C_SCALE_L2E, -C_CLAMP_L2E), C_CLAMP_L2E);
    return exp2_fast(w);
}
// mish(ln s): e^(ln s) == s exactly, so tanh(softplus) = ((1+s)^2-1)/((1+s)^2+1)
static __device__ __forceinline__ float mish_of_ln(float s) {
    float lse = C_LN2 * lg2_fast(s);
    float up  = s + 1.0f;
    float q   = up * up;
    return lse * (q - 1.0f) * rcp_fast(q + 1.0f);
}

// issue one warp-private stage load: 16 rows (4 KB contiguous), XOR-swizzled dst
static __device__ __forceinline__ void load_stage(
    uint32_t dst_base, const float* __restrict__ src, int lane) {
#pragma unroll
    for (int i = 0; i < 8; i++) {
        int idx = i * 32 + lane;            // 256 16B-chunks
        int r = idx >> 4, c = idx & 15;
        cp16(dst_base + (uint32_t)(r * 256 + ((c ^ (r & 7)) << 4)),
             src + (size_t)idx * 4);
    }
}

// ---------------- kernel ----------------
__global__ void __launch_bounds__(THREADS, 2) fused_lin_lse_mish(
    const float* __restrict__ x, const float* __restrict__ W,
    float* __restrict__ out) {
    extern __shared__ char smem[];
    const uint32_t sb = smem_u32(smem);
    const int tid  = threadIdx.x;
    const int lane = tid & 31;
    const int w    = tid >> 5;
    const int g    = lane >> 2;          // 0..7
    const int t    = lane & 3;           // 0..3

    // ---- W -> smem, tf32, XOR-swizzled (chunk ^= row&7) ----
#pragma unroll
    for (int i = 0; i < 16; i++) {
        int idx = i * THREADS + tid;     // 4096 elems
        int r = idx >> 6, c = idx & 63;
        uint32_t off = (uint32_t)(r * 256 + (((c >> 2) ^ (r & 7)) << 4) + (c & 3) * 4);
        *reinterpret_cast<uint32_t*>(smem + off) = f2tf32(W[idx]);
    }
    __syncthreads();                     // only block-wide sync in the kernel

    const size_t wrow0 = (size_t)blockIdx.x * ROWS_PER_CTA + (size_t)w * (CHUNK * NCHUNK);
    const uint32_t wbase = sb + SMEM_X + (uint32_t)w * (STAGES * TILE_BYTES);

    // ---- prologue: fill 3 warp-private stages ----
#pragma unroll
    for (int s = 0; s < STAGES; s++) {
        load_stage(wbase + (uint32_t)s * TILE_BYTES,
                   x + (wrow0 + (size_t)s * CHUNK) * 64, lane);
        CP_COMMIT();
    }

    const uint32_t tquad = (uint32_t)(t * 4);

#pragma unroll
    for (int c = 0; c < NCHUNK; c++) {
        CP_WAIT2();                      // stage c resident (this warp only)

        const uint32_t Ab = (uint32_t)(SMEM_X + w * (STAGES * TILE_BYTES)
                                       + (c % STAGES) * TILE_BYTES);
        float acc[8][4];
#pragma unroll
        for (int nb = 0; nb < 8; nb++)
#pragma unroll
            for (int j = 0; j < 4; j++) acc[nb][j] = 0.0f;

#pragma unroll
        for (int kb = 0; kb < 8; kb++) {
            const uint32_t cx0 = ((((2 * kb) ^ g) << 4)) + tquad;
            const uint32_t cx1 = ((((2 * kb + 1) ^ g) << 4)) + tquad;
            uint32_t a[4];
            a[0] = lds32(smem, Ab + (uint32_t)(g * 256) + cx0);
            a[1] = lds32(smem, Ab + (uint32_t)((g + 8) * 256) + cx0);
            a[2] = lds32(smem, Ab + (uint32_t)(g * 256) + cx1);
            a[3] = lds32(smem, Ab + (uint32_t)((g + 8) * 256) + cx1);
            uint32_t b[8][2];
#pragma unroll
            for (int nb = 0; nb < 8; nb++) {
                uint32_t wrow = (uint32_t)((g + nb * 8) * 256);
                b[nb][0] = lds32(smem, wrow + cx0);
                b[nb][1] = lds32(smem, wrow + cx1);
            }
#pragma unroll
            for (int nb = 0; nb < 8; nb++)
                mma_tf32(acc[nb], a, b[nb]);
        }

        // ---- epilogue: rows g and g+8 of this chunk ----
        float sl = 0.0f, sh = 0.0f;
#pragma unroll
        for (int nb = 0; nb < 8; nb++) {
            sl += expv(acc[nb][0]) + expv(acc[nb][1]);
            sh += expv(acc[nb][2]) + expv(acc[nb][3]);
        }
        sl += __shfl_xor_sync(0xFFFFFFFF, sl, 1);
        sl += __shfl_xor_sync(0xFFFFFFFF, sl, 2);
        sh += __shfl_xor_sync(0xFFFFFFFF, sh, 1);
        sh += __shfl_xor_sync(0xFFFFFFFF, sh, 2);
        if (t == 0) {
            size_t row = wrow0 + (size_t)c * CHUNK + g;
            out[row]     = mish_of_ln(sl);
            out[row + 8] = mish_of_ln(sh);
        }

        // ---- refill the slot just consumed (warp-private; no barrier needed) ----
        if (c + STAGES < NCHUNK)
            load_stage(wbase + (uint32_t)(c % STAGES) * TILE_BYTES,
                       x + (wrow0 + (size_t)(c + STAGES) * CHUNK) * 64, lane);
        CP_COMMIT();                     // commit every iter (empty ok) for uniform counts
    }
}

// ---------------- launch ----------------
extern "C" void kernel_launch(void* const* d_in, const int* in_sizes, int n_in,
                              void* d_out, int out_size) {
    (void)in_sizes; (void)n_in; (void)out_size;
    const float* x = (const float*)d_in[0];
    const float* W = (const float*)d_in[1];
    float* out = (float*)d_out;

    cudaFuncSetAttribute(fused_lin_lse_mish,
                         cudaFuncAttributeMaxDynamicSharedMemorySize, SMEM_TOTAL);
    fused_lin_lse_mish<<<CTAS, THREADS, SMEM_TOTAL>>>(x, W, out);
}